// round 1
// baseline (speedup 1.0000x reference)
#include <cuda_runtime.h>
#include <cuda_bf16.h>
#include <cstdint>

// Problem constants
#define G 8
#define T 4096
#define H 2048
#define E 64
#define GT (G*T)              // 32768 tokens

// Output layout (float32, concatenated in reference return order)
#define DI_OFF 0              // dispatch_indices [G,T,2,2] -> 131072
#define CW_OFF 131072         // combine_weights  [G,T,2]   -> 65536
#define AUX_OFF 196608        // scalar
#define P_OFF 196609          // router_probs [G,T,64] -> 2097152
#define Z_OFF 2293761         // scalar

// -------- scratch (device globals; no allocation allowed) --------
__device__ float g_gate0[GT];
__device__ float g_gate1[GT];
__device__ int   g_e0[GT];
__device__ int   g_e1[GT];
__device__ int   g_sorted[GT];   // per group: token id at sorted rank
__device__ int   g_prio0[GT];
__device__ int   g_prio1[GT];
__device__ float g_zpart[128];
__device__ int   g_cnt[G*E];
__device__ float g_psum[G*E];

// ---------------- K0: zero the atomic counters ----------------
__global__ void k0_zero() {
    int i = blockIdx.x * blockDim.x + threadIdx.x;
    if (i < G*E) g_cnt[i] = 0;
}

// ---------------- K1: GEMM + softmax + top2 + z partials ----------------
// 256 tokens per CTA, 256 threads (1 token/thread), H processed in chunks of 32.
// Accumulators: 64 fp32 logits per thread kept as 32 packed f32x2 (fma.rn.f32x2).
__global__ __launch_bounds__(256) void k1_gemm(
    const float* __restrict__ X, const float* __restrict__ W,
    const float* __restrict__ B, float* __restrict__ out)
{
    __shared__ float xs[256*36];       // x tile [256][36] (pad 36 => 16B-aligned rows, conflict-free)
    __shared__ float ws[32*64];        // w tile [32][64]
    __shared__ float zred[8];

    const int tid  = threadIdx.x;
    const int tok0 = blockIdx.x * 256;

    unsigned long long acc[32];
#pragma unroll
    for (int i = 0; i < 32; ++i) acc[i] = 0ULL;

    const float4* Wv = reinterpret_cast<const float4*>(W);

    for (int hc = 0; hc < H; hc += 32) {
        // load W chunk: 32 rows x 64 floats = 512 float4
#pragma unroll
        for (int i = 0; i < 2; ++i) {
            int idx = tid + i*256;
            reinterpret_cast<float4*>(ws)[idx] = Wv[hc*16 + idx];
        }
        // load X chunk: 256 rows x 32 floats = 2048 float4 (coalesced 128B/row)
#pragma unroll
        for (int k = 0; k < 8; ++k) {
            int i = tid + k*256;
            int r = i >> 3, l = i & 7;
            float4 v = reinterpret_cast<const float4*>(X + (size_t)(tok0 + r)*H + hc)[l];
            float* dst = &xs[r*36 + l*4];
            dst[0]=v.x; dst[1]=v.y; dst[2]=v.z; dst[3]=v.w;
        }
        __syncthreads();

#pragma unroll
        for (int h4 = 0; h4 < 8; ++h4) {
            float4 xv4 = *reinterpret_cast<const float4*>(&xs[tid*36 + h4*4]);
            float xh[4] = {xv4.x, xv4.y, xv4.z, xv4.w};
#pragma unroll
            for (int j = 0; j < 4; ++j) {
                int h = h4*4 + j;
                unsigned xr = __float_as_uint(xh[j]);
                unsigned long long x2;
                asm("mov.b64 %0, {%1, %1};" : "=l"(x2) : "r"(xr));
                const ulonglong2* wp = reinterpret_cast<const ulonglong2*>(ws + h*64);
#pragma unroll
                for (int i = 0; i < 16; ++i) {
                    ulonglong2 wv = wp[i];
                    asm("fma.rn.f32x2 %0, %1, %2, %0;" : "+l"(acc[2*i])   : "l"(x2), "l"(wv.x));
                    asm("fma.rn.f32x2 %0, %1, %2, %0;" : "+l"(acc[2*i+1]) : "l"(x2), "l"(wv.y));
                }
            }
        }
        __syncthreads();
    }

    // ---- epilogue: logits -> softmax -> probs/top2 ----
    float lg[64];
#pragma unroll
    for (int i = 0; i < 32; ++i) {
        lg[2*i]   = __uint_as_float((unsigned)(acc[i] & 0xffffffffULL)) + B[2*i];
        lg[2*i+1] = __uint_as_float((unsigned)(acc[i] >> 32))           + B[2*i+1];
    }
    float mx = lg[0];
#pragma unroll
    for (int e = 1; e < 64; ++e) mx = fmaxf(mx, lg[e]);
    float s = 0.f;
#pragma unroll
    for (int e = 0; e < 64; ++e) { float p = __expf(0.f) * 0.f + expf(lg[e]-mx); lg[e] = p; s += p; }
    float logz = mx + logf(s);
    float inv  = 1.f / s;
#pragma unroll
    for (int e = 0; e < 64; ++e) lg[e] *= inv;

    // top-2 on probs (ties -> lower index first, matching lax.top_k)
    float p0 = -1.f, p1 = -1.f; int i0 = 0, i1 = 0;
#pragma unroll
    for (int e = 0; e < 64; ++e) {
        float v = lg[e];
        if (v > p0) { p1 = p0; i1 = i0; p0 = v; i0 = e; }
        else if (v > p1) { p1 = v; i1 = e; }
    }

    int token = tok0 + tid;
    g_gate0[token] = p0; g_gate1[token] = p1;
    g_e0[token] = i0;    g_e1[token] = i1;
    int g = tok0 >> 12;
    atomicAdd(&g_cnt[g*E + i0], 1);
    atomicAdd(&g_cnt[g*E + i1], 1);

    // write probs via smem transpose for coalesced (if misaligned) stores
    float* P = out + P_OFF;
    for (int half = 0; half < 2; ++half) {
        __syncthreads();
#pragma unroll
        for (int e = 0; e < 32; ++e) xs[tid*33 + e] = lg[half*32 + e];
        __syncthreads();
        int w = tid >> 5, lane = tid & 31;
        for (int r0 = 0; r0 < 32; ++r0) {
            int r = w*32 + r0;
            P[(size_t)(tok0 + r)*64 + half*32 + lane] = xs[r*33 + lane];
        }
    }

    // z-loss partial: deterministic block reduction of logz^2
    float zl = logz * logz;
#pragma unroll
    for (int o = 16; o; o >>= 1) zl += __shfl_xor_sync(0xffffffffu, zl, o);
    if ((tid & 31) == 0) zred[tid >> 5] = zl;
    __syncthreads();
    if (tid == 0) {
        float zz = 0.f;
#pragma unroll
        for (int i = 0; i < 8; ++i) zz += zred[i];
        g_zpart[blockIdx.x] = zz;
    }
}

// ---------------- K2: stable rank by gate0 (descending) ----------------
// grid (16 chunks, 8 groups), 256 threads. Brute-force rank against all 4096.
__global__ __launch_bounds__(256) void k2_rank() {
    __shared__ float gs[T];
    const int tid = threadIdx.x;
    const int grp = blockIdx.y;
    for (int i = tid; i < T; i += 256) gs[i] = g_gate0[grp*T + i];
    __syncthreads();
    const int t = blockIdx.x * 256 + tid;
    const float gi = gs[t];
    int rank = 0;
#pragma unroll 8
    for (int j = 0; j < T; ++j) {
        float gj = gs[j];
        rank += (gj > gi) || (gj == gi && j < t);
    }
    g_sorted[grp*T + rank] = t;
}

// ---------------- K3: expert buffer priorities + dispatch/combine ----------------
// One CTA per group. Sequence: 8192 entries (4096 top-1 in rank order, then 4096 top-2).
__global__ __launch_bounds__(256) void k3_prio(float* __restrict__ out, const int* __restrict__ capPtr) {
    __shared__ short se[2*T];
    __shared__ int hist[8][64];
    __shared__ int base[64];

    const int tid = threadIdx.x;
    const int grp = blockIdx.x;
    const int cap = capPtr ? *capPtr : 160;

    for (int p = tid; p < 2*T; p += 256) {
        int tok = g_sorted[grp*T + (p & (T-1))];
        se[p] = (short)((p < T) ? g_e0[grp*T + tok] : g_e1[grp*T + tok]);
    }
    if (tid < 64) base[tid] = 0;
    __syncthreads();

    const int w = tid >> 5, lane = tid & 31;
    const unsigned lt = (1u << lane) - 1u;

    for (int blk = 0; blk < 32; ++blk) {
        int p = blk*256 + tid;
        int e = se[p];
        for (int i = tid; i < 512; i += 256) (&hist[0][0])[i] = 0;
        __syncthreads();
        unsigned m = __match_any_sync(0xffffffffu, e);
        int lrank = __popc(m & lt);
        if (lane == (__ffs(m) - 1)) hist[w][e] = __popc(m);
        __syncthreads();
        int off = 0;
#pragma unroll
        for (int ww = 0; ww < 8; ++ww) if (ww < w) off += hist[ww][e];
        int prio = base[e] + off + lrank;
        int tok = g_sorted[grp*T + (p & (T-1))];
        if (p < T) g_prio0[grp*T + tok] = prio; else g_prio1[grp*T + tok] = prio;
        __syncthreads();
        if (tid < 64) {
            int ssum = 0;
#pragma unroll
            for (int ww = 0; ww < 8; ++ww) ssum += hist[ww][tid];
            base[tid] += ssum;
        }
        __syncthreads();
    }

    // final per-token outputs for this group
    for (int t = tid; t < T; t += 256) {
        int idx = grp*T + t;
        int e0 = g_e0[idx], e1 = g_e1[idx];
        int pr0 = g_prio0[idx], pr1 = g_prio1[idx];
        float gt0 = g_gate0[idx], gt1 = g_gate1[idx];
        float4 d = make_float4((float)e0, (float)pr0, (float)e1, (float)pr1);
        reinterpret_cast<float4*>(out + DI_OFF)[idx] = d;
        float2 c = make_float2(pr0 < cap ? gt0 : 0.f, pr1 < cap ? gt1 : 0.f);
        reinterpret_cast<float2*>(out + CW_OFF)[idx] = c;
    }
}

// ---------------- K4: deterministic per-(g,e) prob sums ----------------
__global__ __launch_bounds__(256) void k4_psum(const float* __restrict__ out) {
    const float* P = out + P_OFF;
    const int grp = blockIdx.x;
    const int e = threadIdx.x & 63;
    const int q = threadIdx.x >> 6;
    float s = 0.f;
    for (int t = q; t < T; t += 4) s += P[(size_t)(grp*T + t)*64 + e];
    __shared__ float sm[4][64];
    sm[q][e] = s;
    __syncthreads();
    if (threadIdx.x < 64)
        g_psum[grp*E + threadIdx.x] =
            sm[0][threadIdx.x] + sm[1][threadIdx.x] + sm[2][threadIdx.x] + sm[3][threadIdx.x];
}

// ---------------- K5: final scalars ----------------
__global__ void k5_final(float* __restrict__ out) {
    int lane = threadIdx.x;
    float a = 0.f;
    for (int e = lane; e < 64; e += 32)
        for (int g = 0; g < G; ++g)
            a += (float)g_cnt[g*E + e] * g_psum[g*E + e];
#pragma unroll
    for (int o = 16; o; o >>= 1) a += __shfl_xor_sync(0xffffffffu, a, o);
    if (lane == 0) {
        float z = 0.f;
        for (int i = 0; i < 128; ++i) z += g_zpart[i];
        // aux = E/(G*T^2) * sum = sum / 2097152 ; z = sum / (G*T)
        out[AUX_OFF] = a * (1.f / 2097152.f);
        out[Z_OFF]   = z * (1.f / 32768.f);
    }
}

extern "C" void kernel_launch(void* const* d_in, const int* in_sizes, int n_in,
                              void* d_out, int out_size) {
    const float* X = (const float*)d_in[0];
    const float* W = (const float*)d_in[1];
    const float* B = (const float*)d_in[2];
    const int* cap = (n_in > 3) ? (const int*)d_in[3] : nullptr;
    float* out = (float*)d_out;

    k0_zero<<<1, 512>>>();
    k1_gemm<<<GT/256, 256>>>(X, W, B, out);
    k2_rank<<<dim3(16, 8), 256>>>();
    k3_prio<<<G, 256>>>(out, cap);
    k4_psum<<<G, 256>>>(out);
    k5_final<<<1, 32>>>(out);
}

// round 2
// speedup vs baseline: 1.6315x; 1.6315x over previous
#include <cuda_runtime.h>
#include <cuda_bf16.h>
#include <cstdint>

// Problem constants
#define G 8
#define T 4096
#define H 2048
#define E 64
#define GT (G*T)              // 32768 tokens

// Output layout (float32, concatenated in reference return order)
#define DI_OFF 0              // dispatch_indices [G,T,2,2] -> 131072
#define CW_OFF 131072         // combine_weights  [G,T,2]   -> 65536
#define AUX_OFF 196608        // scalar
#define P_OFF 196609          // router_probs [G,T,64] -> 2097152
#define Z_OFF 2293761         // scalar

// K1 tiling
#define KC 16                 // k-chunk
#define NC (H/KC)             // 128 chunks
#define TM 128                // tokens per CTA
#define NCTA (GT/TM)          // 256 CTAs

// -------- scratch (device globals; no allocation allowed) --------
__device__ float g_gate0[GT];
__device__ float g_gate1[GT];
__device__ int   g_e0[GT];
__device__ int   g_e1[GT];
__device__ int   g_sorted[GT];
__device__ int   g_prio0[GT];
__device__ int   g_prio1[GT];
__device__ float g_zpart[NCTA];
__device__ int   g_cnt[G*E];
__device__ float g_psum2[G*8*E];

#define DUP64(d, f) asm("mov.b64 %0, {%1, %1};" : "=l"(d) : "r"(__float_as_uint(f)))
#define FMA2(a, x, w) asm("fma.rn.f32x2 %0, %1, %2, %0;" : "+l"(a) : "l"(x), "l"(w))

// ---------------- K0: zero the atomic counters ----------------
__global__ void k0_zero() {
    int i = blockIdx.x * blockDim.x + threadIdx.x;
    if (i < G*E) g_cnt[i] = 0;
}

// ---------------- K1: GEMM + softmax + top2 + z partials ----------------
// 128 tokens/CTA, 128 threads. Thread (r=tid>>3, c=tid&7) computes tokens
// r*8..r*8+7 x experts c*8..c*8+7 as 32 f32x2 accumulators (token pairs).
// smem: double-buffered xs[2][KC][128] (xor-swizzled) + ws[2][KC][64]
// (granule-swizzled), overlaid later by logits ls[128][68].
__global__ __launch_bounds__(128) void k1_gemm(
    const float* __restrict__ X, const float* __restrict__ W,
    const float* __restrict__ Bv, float* __restrict__ out)
{
    __shared__ __align__(16) float sm[8704];   // max(pipe 6144, ls 8704) floats
    __shared__ float bs[64];
    __shared__ float zred[4];

    const int tid = threadIdx.x;
    const int r = tid >> 3, c = tid & 7;
    const int tok0 = blockIdx.x * TM;
    const int u  = tid >> 2;        // 0..31 (ldg token lane)
    const int h4 = tid & 3;         // 0..3  (ldg float4-in-chunk)

    if (tid < 64) bs[tid] = Bv[tid];

    unsigned long long acc[4][8];
#pragma unroll
    for (int tp = 0; tp < 4; ++tp)
#pragma unroll
        for (int j = 0; j < 8; ++j) acc[tp][j] = 0ULL;

    const float4* Wv4 = reinterpret_cast<const float4*>(W);

    float4 xr[4], wr[2];

    // ---- LDG chunk ch into regs ----
    auto ldg_chunk = [&](int ch) {
        const int hc = ch * KC;
#pragma unroll
        for (int p = 0; p < 4; ++p) {
            int tk = p*32 + u;
            xr[p] = *reinterpret_cast<const float4*>(
                &X[(size_t)(tok0 + tk)*H + hc + h4*4]);
        }
#pragma unroll
        for (int p = 0; p < 2; ++p) {
            int i = p*128 + tid;
            wr[p] = Wv4[(size_t)(hc + (i >> 4))*16 + (i & 15)];
        }
    };

    // ---- STS regs into buffer b ----
    auto sts_chunk = [&](int b) {
        float* xsb = &sm[b * (KC*TM)];
#pragma unroll
        for (int p = 0; p < 4; ++p) {
            int tk = p*32 + u;
            int xb = tk ^ (h4*8);                    // xor swizzle (bank-free)
            xsb[(h4*4 + 0)*TM + xb] = xr[p].x;
            xsb[(h4*4 + 1)*TM + xb] = xr[p].y;
            xsb[(h4*4 + 2)*TM + xb] = xr[p].z;
            xsb[(h4*4 + 3)*TM + xb] = xr[p].w;
        }
        float* wsb = &sm[2*(KC*TM) + b*(KC*64)];
#pragma unroll
        for (int p = 0; p < 2; ++p) {
            int i = p*128 + tid;
            int h = i >> 4, g = i & 15;
            int slot = ((g & 1) << 3) + (g >> 1);    // even granules first
            *reinterpret_cast<float4*>(&wsb[h*64 + slot*4]) = wr[p];
        }
    };

    // ---- compute chunk from buffer b ----
    auto comp_chunk = [&](int b) {
        const float* xsb = &sm[b * (KC*TM)];
        const float* wsb = &sm[2*(KC*TM) + b*(KC*64)];
#pragma unroll
        for (int h = 0; h < KC; ++h) {
            int s = h >> 2;
            const float* xp = &xsb[h*TM + (((r ^ s) & 15) << 3)];
            ulonglong2 xA = *reinterpret_cast<const ulonglong2*>(xp);
            ulonglong2 xB = *reinterpret_cast<const ulonglong2*>(xp + 4);
            const float* wp = &wsb[h*64 + c*4];
            float4 w0 = *reinterpret_cast<const float4*>(wp);        // experts c*8..+3
            float4 w1 = *reinterpret_cast<const float4*>(wp + 32);   // experts c*8+4..+7
            unsigned long long wd[8];
            DUP64(wd[0], w0.x); DUP64(wd[1], w0.y); DUP64(wd[2], w0.z); DUP64(wd[3], w0.w);
            DUP64(wd[4], w1.x); DUP64(wd[5], w1.y); DUP64(wd[6], w1.z); DUP64(wd[7], w1.w);
            unsigned long long xp2[4] = {xA.x, xA.y, xB.x, xB.y};
#pragma unroll
            for (int tp = 0; tp < 4; ++tp)
#pragma unroll
                for (int j = 0; j < 8; ++j)
                    FMA2(acc[tp][j], xp2[tp], wd[j]);
        }
    };

    ldg_chunk(0);
    sts_chunk(0);
    for (int ch = 0; ch < NC; ++ch) {
        if (ch + 1 < NC) ldg_chunk(ch + 1);
        __syncthreads();                 // buffer (ch&1) fully written by all warps
        comp_chunk(ch & 1);
        if (ch + 1 < NC) sts_chunk((ch + 1) & 1);
    }
    __syncthreads();

    // ---- dump accumulators to ls[128][68] ----
#pragma unroll
    for (int tp = 0; tp < 4; ++tp)
#pragma unroll
        for (int j = 0; j < 8; ++j) {
            int t = r*8 + tp*2, e = c*8 + j;
            unsigned long long a = acc[tp][j];
            sm[t*68 + e]     = __uint_as_float((unsigned)(a & 0xffffffffULL));
            sm[(t+1)*68 + e] = __uint_as_float((unsigned)(a >> 32));
        }
    __syncthreads();

    // ---- per-token epilogue (1 token per thread) ----
    const int t = tid;
    float lg[64];
#pragma unroll
    for (int e = 0; e < 64; ++e) lg[e] = sm[t*68 + e] + bs[e];

    float mx = lg[0];
#pragma unroll
    for (int e = 1; e < 64; ++e) mx = fmaxf(mx, lg[e]);
    float ssum = 0.f;
#pragma unroll
    for (int e = 0; e < 64; ++e) { float p = expf(lg[e] - mx); lg[e] = p; ssum += p; }
    float logz = mx + logf(ssum);
    float inv  = 1.f / ssum;
#pragma unroll
    for (int e = 0; e < 64; ++e) lg[e] *= inv;

    float p0 = -1.f, p1 = -1.f; int i0 = 0, i1 = 0;
#pragma unroll
    for (int e = 0; e < 64; ++e) {
        float v = lg[e];
        if (v > p0) { p1 = p0; i1 = i0; p0 = v; i0 = e; }
        else if (v > p1) { p1 = v; i1 = e; }
    }

    const int token = tok0 + t;
    g_gate0[token] = p0; g_gate1[token] = p1;
    g_e0[token] = i0;    g_e1[token] = i1;
    const int grp = token >> 12;
    atomicAdd(&g_cnt[grp*E + i0], 1);
    atomicAdd(&g_cnt[grp*E + i1], 1);

    // probs back to ls, then coalesced scalar copy-out (P base is 4B-aligned only)
#pragma unroll
    for (int e = 0; e < 64; ++e) sm[t*68 + e] = lg[e];

    // z partial (4 warps)
    float zl = logz * logz;
#pragma unroll
    for (int o = 16; o; o >>= 1) zl += __shfl_xor_sync(0xffffffffu, zl, o);
    if ((tid & 31) == 0) zred[tid >> 5] = zl;
    __syncthreads();

    float* P = out + P_OFF + (size_t)tok0*64;
    for (int k = tid; k < TM*64; k += 128) P[k] = sm[(k >> 6)*68 + (k & 63)];

    if (tid == 0)
        g_zpart[blockIdx.x] = zred[0] + zred[1] + zred[2] + zred[3];
}

// ---------------- K2: stable rank by gate0 (descending) ----------------
__global__ __launch_bounds__(256) void k2_rank() {
    __shared__ float gs[T];
    const int tid = threadIdx.x;
    const int grp = blockIdx.y;
    for (int i = tid; i < T; i += 256) gs[i] = g_gate0[grp*T + i];
    __syncthreads();
    const int t = blockIdx.x * 256 + tid;
    const float gi = gs[t];
    int rank = 0;
#pragma unroll 8
    for (int j = 0; j < T; ++j) {
        float gj = gs[j];
        rank += (gj > gi) || (gj == gi && j < t);
    }
    g_sorted[grp*T + rank] = t;
}

// ---------------- K3: expert buffer priorities + dispatch/combine ----------------
__global__ __launch_bounds__(256) void k3_prio(float* __restrict__ out, const int* __restrict__ capPtr) {
    __shared__ short se[2*T];
    __shared__ int hist[8][64];
    __shared__ int base[64];

    const int tid = threadIdx.x;
    const int grp = blockIdx.x;
    const int cap = capPtr ? *capPtr : 160;

    for (int p = tid; p < 2*T; p += 256) {
        int tok = g_sorted[grp*T + (p & (T-1))];
        se[p] = (short)((p < T) ? g_e0[grp*T + tok] : g_e1[grp*T + tok]);
    }
    if (tid < 64) base[tid] = 0;
    __syncthreads();

    const int w = tid >> 5, lane = tid & 31;
    const unsigned lt = (1u << lane) - 1u;

    for (int blk = 0; blk < 32; ++blk) {
        int p = blk*256 + tid;
        int e = se[p];
        for (int i = tid; i < 512; i += 256) (&hist[0][0])[i] = 0;
        __syncthreads();
        unsigned m = __match_any_sync(0xffffffffu, e);
        int lrank = __popc(m & lt);
        if (lane == (__ffs(m) - 1)) hist[w][e] = __popc(m);
        __syncthreads();
        int off = 0;
#pragma unroll
        for (int ww = 0; ww < 8; ++ww) if (ww < w) off += hist[ww][e];
        int prio = base[e] + off + lrank;
        int tok = g_sorted[grp*T + (p & (T-1))];
        if (p < T) g_prio0[grp*T + tok] = prio; else g_prio1[grp*T + tok] = prio;
        __syncthreads();
        if (tid < 64) {
            int ssum = 0;
#pragma unroll
            for (int ww = 0; ww < 8; ++ww) ssum += hist[ww][tid];
            base[tid] += ssum;
        }
        __syncthreads();
    }

    for (int t = tid; t < T; t += 256) {
        int idx = grp*T + t;
        int e0 = g_e0[idx], e1 = g_e1[idx];
        int pr0 = g_prio0[idx], pr1 = g_prio1[idx];
        float gt0 = g_gate0[idx], gt1 = g_gate1[idx];
        float4 d = make_float4((float)e0, (float)pr0, (float)e1, (float)pr1);
        reinterpret_cast<float4*>(out + DI_OFF)[idx] = d;
        float2 cc = make_float2(pr0 < cap ? gt0 : 0.f, pr1 < cap ? gt1 : 0.f);
        reinterpret_cast<float2*>(out + CW_OFF)[idx] = cc;
    }
}

// ---------------- K4: deterministic per-(g,chunk,e) prob partial sums ----------------
__global__ __launch_bounds__(256) void k4_psum(const float* __restrict__ out) {
    const float* P = out + P_OFF;
    const int grp = blockIdx.x;
    const int ch  = blockIdx.y;
    const int e = threadIdx.x & 63;
    const int q = threadIdx.x >> 6;
    float s = 0.f;
    const int t0 = ch * 512;
    for (int t = t0 + q; t < t0 + 512; t += 4)
        s += P[(size_t)(grp*T + t)*64 + e];
    __shared__ float smr[4][64];
    smr[q][e] = s;
    __syncthreads();
    if (threadIdx.x < 64)
        g_psum2[(grp*8 + ch)*64 + threadIdx.x] =
            smr[0][threadIdx.x] + smr[1][threadIdx.x] +
            smr[2][threadIdx.x] + smr[3][threadIdx.x];
}

// ---------------- K5: final scalars ----------------
__global__ void k5_final(float* __restrict__ out) {
    int lane = threadIdx.x;
    float a = 0.f;
    for (int e = lane; e < 64; e += 32)
        for (int g = 0; g < G; ++g) {
            float ps = 0.f;
#pragma unroll
            for (int ch = 0; ch < 8; ++ch) ps += g_psum2[(g*8 + ch)*64 + e];
            a += (float)g_cnt[g*E + e] * ps;
        }
#pragma unroll
    for (int o = 16; o; o >>= 1) a += __shfl_xor_sync(0xffffffffu, a, o);
    if (lane == 0) {
        float z = 0.f;
        for (int i = 0; i < NCTA; ++i) z += g_zpart[i];
        out[AUX_OFF] = a * (1.f / 2097152.f);
        out[Z_OFF]   = z * (1.f / 32768.f);
    }
}

extern "C" void kernel_launch(void* const* d_in, const int* in_sizes, int n_in,
                              void* d_out, int out_size) {
    const float* X = (const float*)d_in[0];
    const float* W = (const float*)d_in[1];
    const float* B = (const float*)d_in[2];
    const int* cap = (n_in > 3) ? (const int*)d_in[3] : nullptr;
    float* out = (float*)d_out;

    k0_zero<<<1, 512>>>();
    k1_gemm<<<NCTA, 128>>>(X, W, B, out);
    k2_rank<<<dim3(16, 8), 256>>>();
    k3_prio<<<G, 256>>>(out, cap);
    k4_psum<<<dim3(8, 8), 256>>>(out);
    k5_final<<<1, 32>>>(out);
}